// round 2
// baseline (speedup 1.0000x reference)
#include <cuda_runtime.h>

#define NROWS 8192
#define D 512
#define D4 (D / 4)          // 128 float4 per row
#define NBLOCKS 1024        // 8 warps/block * 1024 = 8192 rows
#define NTHREADS 256

// Allocation-free scratch: device globals.
__device__ float g_partials[NBLOCKS];
__device__ unsigned int g_count = 0;

__global__ __launch_bounds__(NTHREADS) void byol_fused_kernel(
    const float4* __restrict__ x, const float4* __restrict__ xt,
    float* __restrict__ out)
{
    __shared__ float s_cos[NTHREADS / 32];   // one cosine per warp
    __shared__ bool  s_is_last;

    int warp_in_blk = threadIdx.x >> 5;
    int lane        = threadIdx.x & 31;
    int row         = blockIdx.x * (NTHREADS / 32) + warp_in_blk;

    const float4* xr = x  + (size_t)row * D4;
    const float4* tr = xt + (size_t)row * D4;

    float dot = 0.f, nx = 0.f, nt = 0.f;
    #pragma unroll
    for (int i = 0; i < 4; i++) {
        float4 a = xr[lane + i * 32];
        float4 b = tr[lane + i * 32];
        dot += a.x * b.x + a.y * b.y + a.z * b.z + a.w * b.w;
        nx  += a.x * a.x + a.y * a.y + a.z * a.z + a.w * a.w;
        nt  += b.x * b.x + b.y * b.y + b.z * b.z + b.w * b.w;
    }

    // Warp tree reduction (deterministic order).
    #pragma unroll
    for (int off = 16; off > 0; off >>= 1) {
        dot += __shfl_xor_sync(0xffffffffu, dot, off);
        nx  += __shfl_xor_sync(0xffffffffu, nx,  off);
        nt  += __shfl_xor_sync(0xffffffffu, nt,  off);
    }

    if (lane == 0) {
        const float EPS = 1e-8f;
        float denom = fmaxf(sqrtf(nx), EPS) * fmaxf(sqrtf(nt), EPS);
        s_cos[warp_in_blk] = dot / denom;
    }
    __syncthreads();

    // One thread reduces the 8 warp cosines and publishes the block partial.
    if (threadIdx.x == 0) {
        float p = 0.f;
        #pragma unroll
        for (int i = 0; i < NTHREADS / 32; i++) p += s_cos[i];
        g_partials[blockIdx.x] = p;
        __threadfence();
        unsigned int prev = atomicInc(&g_count, NBLOCKS - 1);
        s_is_last = (prev == NBLOCKS - 1);
        // atomicInc with limit NBLOCKS-1 wraps the counter back to 0
        // automatically on the last block -> graph-replay safe.
    }
    __syncthreads();

    if (!s_is_last) return;

    // Last block: sum all 1024 block partials in a fixed order.
    __shared__ float sbuf[NTHREADS];
    float s = 0.f;
    #pragma unroll
    for (int i = 0; i < NBLOCKS / NTHREADS; i++)
        s += g_partials[threadIdx.x + i * NTHREADS];
    sbuf[threadIdx.x] = s;
    __syncthreads();

    #pragma unroll
    for (int stride = NTHREADS / 2; stride > 0; stride >>= 1) {
        if (threadIdx.x < stride) sbuf[threadIdx.x] += sbuf[threadIdx.x + stride];
        __syncthreads();
    }

    if (threadIdx.x == 0)
        out[0] = 2.0f - 2.0f * (sbuf[0] / (float)NROWS);
}

extern "C" void kernel_launch(void* const* d_in, const int* in_sizes, int n_in,
                              void* d_out, int out_size)
{
    const float4* x  = (const float4*)d_in[0];
    const float4* xt = (const float4*)d_in[1];
    float* out = (float*)d_out;

    byol_fused_kernel<<<NBLOCKS, NTHREADS>>>(x, xt, out);
}

// round 3
// speedup vs baseline: 1.9810x; 1.9810x over previous
#include <cuda_runtime.h>

#define NROWS 8192
#define D4 128              // 512 floats = 128 float4 per row
#define NBLOCKS 512         // single wave on 148 SMs @ 4 blocks/SM
#define NTHREADS 256
#define WARPS_PER_BLK 8
#define ROWS_PER_WARP 2     // 512 * 8 * 2 = 8192 rows

// Single 64-bit accumulator:
//   bits [52:64) : block-arrival counter (max 512, fits easily)
//   bits [0:52)  : biased fixed-point sum of cosines (scale 2^32, bias 2^40/block)
// Integer adds are exactly associative -> deterministic result for any atomic order.
__device__ unsigned long long g_accum = 0ull;

__global__ __launch_bounds__(NTHREADS) void byol_onepass_kernel(
    const float4* __restrict__ x, const float4* __restrict__ xt,
    float* __restrict__ out)
{
    __shared__ float s_part[WARPS_PER_BLK];

    int warp = threadIdx.x >> 5;
    int lane = threadIdx.x & 31;
    int row0 = (blockIdx.x * WARPS_PER_BLK + warp) * ROWS_PER_WARP;

    float csum = 0.f;   // lane 0 accumulates this warp's cosines

    #pragma unroll
    for (int r = 0; r < ROWS_PER_WARP; r++) {
        const float4* xr = x  + (size_t)(row0 + r) * D4;
        const float4* tr = xt + (size_t)(row0 + r) * D4;

        float dot = 0.f, nx = 0.f, nt = 0.f;
        #pragma unroll
        for (int i = 0; i < 4; i++) {
            float4 a = xr[lane + i * 32];
            float4 b = tr[lane + i * 32];
            dot += a.x * b.x + a.y * b.y + a.z * b.z + a.w * b.w;
            nx  += a.x * a.x + a.y * a.y + a.z * a.z + a.w * a.w;
            nt  += b.x * b.x + b.y * b.y + b.z * b.z + b.w * b.w;
        }

        // Warp tree reduction (fixed order -> deterministic).
        #pragma unroll
        for (int off = 16; off > 0; off >>= 1) {
            dot += __shfl_xor_sync(0xffffffffu, dot, off);
            nx  += __shfl_xor_sync(0xffffffffu, nx,  off);
            nt  += __shfl_xor_sync(0xffffffffu, nt,  off);
        }

        if (lane == 0) {
            const float EPS = 1e-8f;
            float denom = fmaxf(sqrtf(nx), EPS) * fmaxf(sqrtf(nt), EPS);
            csum += dot / denom;
        }
    }

    if (lane == 0) s_part[warp] = csum;
    __syncthreads();

    if (threadIdx.x == 0) {
        // Block partial in double (exact fixed-point conversion).
        double p = 0.0;
        #pragma unroll
        for (int i = 0; i < WARPS_PER_BLK; i++) p += (double)s_part[i];

        long long fixed = llrint(p * 4294967296.0);          // * 2^32
        // |p| <= 16 -> |fixed| < 2^37; bias 2^40 keeps it positive.
        unsigned long long add =
            (1ull << 52) + (unsigned long long)(fixed + (1ll << 40));

        unsigned long long old   = atomicAdd(&g_accum, add);
        unsigned long long total = old + add;

        if ((total >> 52) == (unsigned long long)NBLOCKS) {
            // This block's atomic was the last in L2 serialization order:
            // 'total' holds the complete, exact integer sum. No fence needed.
            long long sfix = (long long)(total & ((1ull << 52) - 1))
                           - ((long long)NBLOCKS << 40);     // remove biases
            double cos_sum = (double)sfix * (1.0 / 4294967296.0);
            out[0] = (float)(2.0 - 2.0 * cos_sum / (double)NROWS);
            // All contributions are in; safe to reset for the next graph replay.
            atomicExch(&g_accum, 0ull);
        }
    }
}

extern "C" void kernel_launch(void* const* d_in, const int* in_sizes, int n_in,
                              void* d_out, int out_size)
{
    const float4* x  = (const float4*)d_in[0];
    const float4* xt = (const float4*)d_in[1];
    float* out = (float*)d_out;

    byol_onepass_kernel<<<NBLOCKS, NTHREADS>>>(x, xt, out);
}